// round 2
// baseline (speedup 1.0000x reference)
#include <cuda_runtime.h>
#include <math.h>

#define DIM   2048
#define SEQ   3072
#define NH    16
#define HD    128
#define RANK  16
#define EPS_  1e-6f

// ---------------- scratch (static device memory; no allocs) ----------------
__device__ float g_weff[4][DIM * DIM];   // effective weights (W + scale * lup@ldown)
__device__ float g_q[SEQ * DIM];
__device__ float g_k[SEQ * DIM];
__device__ float g_v[SEQ * DIM];
__device__ float g_o[SEQ * DIM];

// ---------------- 1) effective weight prep -------------------------------
// out[j,k] = w[j,k] + scale * sum_r lup[j,r] * ldown[r,k]
__global__ __launch_bounds__(256) void prep_weff(const float* __restrict__ w,
                                                 const float* __restrict__ ldown,
                                                 const float* __restrict__ lup,
                                                 float* __restrict__ out,
                                                 float scale)
{
    int k = blockIdx.x * 256 + threadIdx.x;   // 0..2047
    int j = blockIdx.y;                        // 0..2047
    float acc = 0.f;
#pragma unroll
    for (int r = 0; r < RANK; r++)
        acc += lup[j * RANK + r] * ldown[r * DIM + k];
    out[j * DIM + k] = w[j * DIM + k] + scale * acc;
}

// ---------------- 2) SGEMM: C[m,n] = sum_k A[m,k]*B[n,k] + bias[n] --------
// A: [M,K] row-major, B: [N,K] row-major (NT GEMM). 128x128x8 tile, 8x8/thread.
#define BM 128
#define BN 128
#define BK 8

__global__ __launch_bounds__(256) void sgemm_bias(const float* __restrict__ A,
                                                  const float* __restrict__ B,
                                                  const float* __restrict__ bias,
                                                  float* __restrict__ C,
                                                  int M, int N, int K)
{
    __shared__ float As[BK][BM];
    __shared__ float Bs[BK][BN];

    const int tid = threadIdx.x;
    const int m0 = blockIdx.y * BM;
    const int n0 = blockIdx.x * BN;

    const int lr = tid >> 1;            // 0..127: row within tile for loads
    const int lc = (tid & 1) * 4;       // 0 or 4: k offset (float4)
    const int tr = tid >> 4;            // 0..15
    const int tc = tid & 15;            // 0..15

    float acc[8][8] = {};

    const float* Ap = A + (size_t)(m0 + lr) * K + lc;
    const float* Bp = B + (size_t)(n0 + lr) * K + lc;

    for (int k0 = 0; k0 < K; k0 += BK) {
        float4 av = *(const float4*)(Ap + k0);
        float4 bv = *(const float4*)(Bp + k0);
        As[lc + 0][lr] = av.x; As[lc + 1][lr] = av.y;
        As[lc + 2][lr] = av.z; As[lc + 3][lr] = av.w;
        Bs[lc + 0][lr] = bv.x; Bs[lc + 1][lr] = bv.y;
        Bs[lc + 2][lr] = bv.z; Bs[lc + 3][lr] = bv.w;
        __syncthreads();

#pragma unroll
        for (int k = 0; k < BK; k++) {
            float4 a0 = *(const float4*)&As[k][tr * 8];
            float4 a1 = *(const float4*)&As[k][tr * 8 + 4];
            float4 b0 = *(const float4*)&Bs[k][tc * 8];
            float4 b1 = *(const float4*)&Bs[k][tc * 8 + 4];
            float af[8] = {a0.x, a0.y, a0.z, a0.w, a1.x, a1.y, a1.z, a1.w};
            float bf[8] = {b0.x, b0.y, b0.z, b0.w, b1.x, b1.y, b1.z, b1.w};
#pragma unroll
            for (int i = 0; i < 8; i++)
#pragma unroll
                for (int j = 0; j < 8; j++)
                    acc[i][j] += af[i] * bf[j];
        }
        __syncthreads();
    }

    float bj[8];
#pragma unroll
    for (int j = 0; j < 8; j++) bj[j] = bias[n0 + tc * 8 + j];

#pragma unroll
    for (int i = 0; i < 8; i++) {
        float* crow = C + (size_t)(m0 + tr * 8 + i) * N + n0 + tc * 8;
        float4 r0 = make_float4(acc[i][0] + bj[0], acc[i][1] + bj[1],
                                acc[i][2] + bj[2], acc[i][3] + bj[3]);
        float4 r1 = make_float4(acc[i][4] + bj[4], acc[i][5] + bj[5],
                                acc[i][6] + bj[6], acc[i][7] + bj[7]);
        *(float4*)(crow)     = r0;
        *(float4*)(crow + 4) = r1;
    }
}

// ---------------- 3) RMSNorm (over D=2048) + interleaved RoPE, in place ---
__global__ __launch_bounds__(256) void rmsnorm_rope(float* __restrict__ X,
                                                    const float* __restrict__ w,
                                                    const float* __restrict__ fcos,
                                                    const float* __restrict__ fsin)
{
    const int s = blockIdx.x;
    const int tid = threadIdx.x;
    __shared__ float red[256];

    float* row = X + (size_t)s * DIM;
    float ss = 0.f;
#pragma unroll
    for (int i = tid; i < DIM; i += 256) { float v = row[i]; ss += v * v; }
    red[tid] = ss;
    __syncthreads();
    for (int st = 128; st > 0; st >>= 1) {
        if (tid < st) red[tid] += red[tid + st];
        __syncthreads();
    }
    const float rs = rsqrtf(red[0] / (float)DIM + EPS_);

    // 1024 pairs; pair p lives in head-dim pair (p % 64)
#pragma unroll
    for (int p = tid; p < DIM / 2; p += 256) {
        int hp = p & 63;
        float c  = fcos[s * HD + 2 * hp];
        float sn = fsin[s * HD + 2 * hp + 1];
        float x1 = row[2 * p]     * rs * w[2 * p];
        float x2 = row[2 * p + 1] * rs * w[2 * p + 1];
        row[2 * p]     = x1 * c - x2 * sn;
        row[2 * p + 1] = x1 * sn + x2 * c;
    }
}

// ---------------- 4) flash attention (fp32, online softmax) --------------
// grid: (SEQ/64, NH). block: 256. BM=BN=64, HD=128.
// smem float offsets:
#define QS_OFF 0        // [128][68] transposed (Qs[d][r]), pre-scaled
#define KS_OFF 8704     // [128][68] transposed
#define VS_OFF 17408    // [64][128]
#define SS_OFF 25600    // [64][65]
#define MS_OFF 29760    // [64]
#define LS_OFF 29824    // [64]
#define AL_OFF 29888    // [64]
#define FLASH_SMEM_FLOATS 29952

__global__ __launch_bounds__(256) void flash_attn(const float* __restrict__ Q,
                                                  const float* __restrict__ K,
                                                  const float* __restrict__ V,
                                                  float* __restrict__ O)
{
    extern __shared__ float sm[];
    float* smQ = sm + QS_OFF;
    float* smK = sm + KS_OFF;
    float* smV = sm + VS_OFF;
    float* smS = sm + SS_OFF;
    float* smM = sm + MS_OFF;
    float* smL = sm + LS_OFF;
    float* smA = sm + AL_OFF;

    const int tid = threadIdx.x;
    const int qt = blockIdx.x;
    const int h  = blockIdx.y;
    const int tr = tid >> 4;          // 0..15 -> rows tr*4..tr*4+3
    const int tc = tid & 15;          // 0..15 -> S cols tc*4.. / O dims tc*8..
    const int tr4 = tr * 4;
    const int tc4 = tc * 4;
    const int tc8 = tc * 8;
    const float scale = 0.08838834764831845f;   // 1/sqrt(128)

    // load Q tile, transposed + pre-scaled
    const size_t qbase = (size_t)(qt * 64) * DIM + h * HD;
    for (int e = tid; e < 64 * HD; e += 256) {
        int r = e >> 7, d = e & 127;
        smQ[d * 68 + r] = Q[qbase + (size_t)r * DIM + d] * scale;
    }
    if (tid < 64) { smM[tid] = -1e30f; smL[tid] = 0.f; }

    float acc[4][8] = {};
    __syncthreads();

    for (int kt = 0; kt < SEQ / 64; kt++) {
        const size_t kbase = (size_t)(kt * 64) * DIM + h * HD;
        for (int e = tid; e < 64 * HD; e += 256) {
            int r = e >> 7, d = e & 127;
            smK[d * 68 + r] = K[kbase + (size_t)r * DIM + d];
        }
        for (int e = tid; e < 64 * (HD / 4); e += 256) {
            int r = e >> 5, d4 = (e & 31) * 4;
            *(float4*)&smV[r * HD + d4] = *(const float4*)(V + kbase + (size_t)r * DIM + d4);
        }
        __syncthreads();

        // S = Qs^T Ks : each thread 4x4
        float s4[4][4] = {};
#pragma unroll 8
        for (int k = 0; k < HD; k++) {
            float4 qa = *(const float4*)&smQ[k * 68 + tr4];
            float4 kb = *(const float4*)&smK[k * 68 + tc4];
            float qf[4] = {qa.x, qa.y, qa.z, qa.w};
            float kf[4] = {kb.x, kb.y, kb.z, kb.w};
#pragma unroll
            for (int i = 0; i < 4; i++)
#pragma unroll
                for (int j = 0; j < 4; j++)
                    s4[i][j] += qf[i] * kf[j];
        }
#pragma unroll
        for (int i = 0; i < 4; i++)
#pragma unroll
            for (int j = 0; j < 4; j++)
                smS[(tr4 + i) * 65 + tc4 + j] = s4[i][j];
        __syncthreads();

        // online softmax: one thread per row
        if (tid < 64) {
            float* srow = &smS[tid * 65];
            float mold = smM[tid];
            float mx = mold;
#pragma unroll 8
            for (int j = 0; j < 64; j++) mx = fmaxf(mx, srow[j]);
            float alpha = __expf(mold - mx);
            float sum = 0.f;
#pragma unroll 8
            for (int j = 0; j < 64; j++) {
                float p = __expf(srow[j] - mx);
                srow[j] = p;
                sum += p;
            }
            smL[tid] = smL[tid] * alpha + sum;
            smM[tid] = mx;
            smA[tid] = alpha;
        }
        __syncthreads();

        // rescale accumulators and accumulate P*V
        float al[4];
#pragma unroll
        for (int i = 0; i < 4; i++) al[i] = smA[tr4 + i];
#pragma unroll
        for (int i = 0; i < 4; i++)
#pragma unroll
            for (int d = 0; d < 8; d++) acc[i][d] *= al[i];

#pragma unroll 4
        for (int j = 0; j < 64; j++) {
            float4 v0 = *(const float4*)&smV[j * HD + tc8];
            float4 v1 = *(const float4*)&smV[j * HD + tc8 + 4];
#pragma unroll
            for (int i = 0; i < 4; i++) {
                float p = smS[(tr4 + i) * 65 + j];
                acc[i][0] += p * v0.x; acc[i][1] += p * v0.y;
                acc[i][2] += p * v0.z; acc[i][3] += p * v0.w;
                acc[i][4] += p * v1.x; acc[i][5] += p * v1.y;
                acc[i][6] += p * v1.z; acc[i][7] += p * v1.w;
            }
        }
        __syncthreads();
    }

    // epilogue: O[s, h*HD + d] = acc / l
#pragma unroll
    for (int i = 0; i < 4; i++) {
        float inv = 1.0f / smL[tr4 + i];
        float* orow = O + (size_t)(qt * 64 + tr4 + i) * DIM + h * HD + tc8;
        float4 r0 = make_float4(acc[i][0] * inv, acc[i][1] * inv,
                                acc[i][2] * inv, acc[i][3] * inv);
        float4 r1 = make_float4(acc[i][4] * inv, acc[i][5] * inv,
                                acc[i][6] * inv, acc[i][7] * inv);
        *(float4*)(orow)     = r0;
        *(float4*)(orow + 4) = r1;
    }
}

// ---------------- launch ---------------------------------------------------
static float* symaddr(const void* sym)
{
    void* p = nullptr;
    cudaGetSymbolAddress(&p, sym);
    return (float*)p;
}

extern "C" void kernel_launch(void* const* d_in, const int* in_sizes, int n_in,
                              void* d_out, int out_size)
{
    const float* x       = (const float*)d_in[0];
    const float* wq      = (const float*)d_in[1];
    const float* bq      = (const float*)d_in[2];
    const float* wk      = (const float*)d_in[3];
    const float* bk      = (const float*)d_in[4];
    const float* wv      = (const float*)d_in[5];
    const float* bv      = (const float*)d_in[6];
    const float* wo      = (const float*)d_in[7];
    const float* bo      = (const float*)d_in[8];
    const float* lq_down = (const float*)d_in[9];
    const float* lq_up   = (const float*)d_in[10];
    const float* lk_down = (const float*)d_in[11];
    const float* lk_up   = (const float*)d_in[12];
    const float* lv_down = (const float*)d_in[13];
    const float* lv_up   = (const float*)d_in[14];
    const float* lo_down = (const float*)d_in[15];
    const float* lo_up   = (const float*)d_in[16];
    const float* nq_w    = (const float*)d_in[17];
    const float* nk_w    = (const float*)d_in[18];
    const float* fcos    = (const float*)d_in[19];
    const float* fsin    = (const float*)d_in[20];

    float* weff = symaddr(g_weff);
    float* q = symaddr(g_q);
    float* k = symaddr(g_k);
    float* v = symaddr(g_v);
    float* o = symaddr(g_o);

    const size_t smem_bytes = FLASH_SMEM_FLOATS * sizeof(float);
    cudaFuncSetAttribute(flash_attn, cudaFuncAttributeMaxDynamicSharedMemorySize,
                         (int)smem_bytes);

    const float scale = 16.0f / (float)RANK;   // ALPHA / R = 1.0

    dim3 pg(DIM / 256, DIM);
    prep_weff<<<pg, 256>>>(wq, lq_down, lq_up, weff + 0 * (size_t)DIM * DIM, scale);
    prep_weff<<<pg, 256>>>(wk, lk_down, lk_up, weff + 1 * (size_t)DIM * DIM, scale);
    prep_weff<<<pg, 256>>>(wv, lv_down, lv_up, weff + 2 * (size_t)DIM * DIM, scale);
    prep_weff<<<pg, 256>>>(wo, lo_down, lo_up, weff + 3 * (size_t)DIM * DIM, scale);

    dim3 gg(DIM / BN, SEQ / BM);
    sgemm_bias<<<gg, 256>>>(x, weff + 0 * (size_t)DIM * DIM, bq, q, SEQ, DIM, DIM);
    sgemm_bias<<<gg, 256>>>(x, weff + 1 * (size_t)DIM * DIM, bk, k, SEQ, DIM, DIM);
    sgemm_bias<<<gg, 256>>>(x, weff + 2 * (size_t)DIM * DIM, bv, v, SEQ, DIM, DIM);

    rmsnorm_rope<<<SEQ, 256>>>(q, nq_w, fcos, fsin);
    rmsnorm_rope<<<SEQ, 256>>>(k, nk_w, fcos, fsin);

    dim3 ag(SEQ / 64, NH);
    flash_attn<<<ag, 256, smem_bytes>>>(q, k, v, o);

    sgemm_bias<<<gg, 256>>>(o, weff + 3 * (size_t)DIM * DIM, bo, (float*)d_out,
                            SEQ, DIM, DIM);
}

// round 5
// speedup vs baseline: 1.3543x; 1.3543x over previous
#include <cuda_runtime.h>
#include <cuda_bf16.h>
#include <math.h>
#include <stdint.h>

#define DIM   2048
#define SEQ   3072
#define NH    16
#define HD    128
#define RANK  16
#define EPS_  1e-6f

// ---------------- scratch (static device memory; no allocs) ----------------
__device__ __nv_bfloat16 g_xhi[SEQ * DIM];
__device__ __nv_bfloat16 g_xlo[SEQ * DIM];
__device__ __nv_bfloat16 g_whi[4][DIM * DIM];
__device__ __nv_bfloat16 g_wlo[4][DIM * DIM];
__device__ __nv_bfloat16 g_ohi[SEQ * DIM];
__device__ __nv_bfloat16 g_olo[SEQ * DIM];
__device__ float g_q[SEQ * DIM];
__device__ float g_k[SEQ * DIM];
__device__ float g_v[SEQ * DIM];
__device__ float g_o[SEQ * DIM];

// ---------------- PTX helpers ---------------------------------------------
__device__ __forceinline__ uint32_t smem_u32(const void* p)
{
    uint32_t a;
    asm("{ .reg .u64 t; cvta.to.shared.u64 t, %1; cvt.u32.u64 %0, t; }"
        : "=r"(a) : "l"(p));
    return a;
}

__device__ __forceinline__ void cp_async16(uint32_t s, const void* g)
{
    asm volatile("cp.async.cg.shared.global [%0], [%1], 16;" :: "r"(s), "l"(g));
}

__device__ __forceinline__ void cp_commit()
{
    asm volatile("cp.async.commit_group;" ::: "memory");
}

template <int N>
__device__ __forceinline__ void cp_wait()
{
    asm volatile("cp.async.wait_group %0;" :: "n"(N) : "memory");
}

__device__ __forceinline__ void ldsm_x4(uint32_t addr, uint32_t& r0, uint32_t& r1,
                                        uint32_t& r2, uint32_t& r3)
{
    asm volatile("ldmatrix.sync.aligned.m8n8.x4.shared.b16 {%0,%1,%2,%3}, [%4];"
                 : "=r"(r0), "=r"(r1), "=r"(r2), "=r"(r3) : "r"(addr));
}

__device__ __forceinline__ void mma_bf16(float& c0, float& c1, float& c2, float& c3,
                                         uint32_t a0, uint32_t a1, uint32_t a2,
                                         uint32_t a3, uint32_t b0, uint32_t b1)
{
    asm volatile(
        "mma.sync.aligned.m16n8k16.row.col.f32.bf16.bf16.f32 "
        "{%0,%1,%2,%3}, {%4,%5,%6,%7}, {%8,%9}, {%0,%1,%2,%3};"
        : "+f"(c0), "+f"(c1), "+f"(c2), "+f"(c3)
        : "r"(a0), "r"(a1), "r"(a2), "r"(a3), "r"(b0), "r"(b1));
}

// ---------------- 1) effective weight prep + bf16 split --------------------
__global__ __launch_bounds__(256) void prep_weff_split(const float* __restrict__ w,
                                                       const float* __restrict__ ldown,
                                                       const float* __restrict__ lup,
                                                       __nv_bfloat16* __restrict__ hi,
                                                       __nv_bfloat16* __restrict__ lo,
                                                       float scale)
{
    int kx = blockIdx.x * 256 + threadIdx.x;
    int j  = blockIdx.y;
    float acc = 0.f;
#pragma unroll
    for (int r = 0; r < RANK; r++)
        acc += lup[j * RANK + r] * ldown[r * DIM + kx];
    float v = w[j * DIM + kx] + scale * acc;
    __nv_bfloat16 h = __float2bfloat16(v);
    hi[j * DIM + kx] = h;
    lo[j * DIM + kx] = __float2bfloat16(v - __bfloat162float(h));
}

// ---------------- 2) fp32 -> bf16 hi/lo split -------------------------------
__global__ __launch_bounds__(256) void split_bf16(const float* __restrict__ in,
                                                  __nv_bfloat16* __restrict__ hi,
                                                  __nv_bfloat16* __restrict__ lo,
                                                  int n)
{
    int i = blockIdx.x * 256 + threadIdx.x;
    if (i < n) {
        float v = in[i];
        __nv_bfloat16 h = __float2bfloat16(v);
        hi[i] = h;
        lo[i] = __float2bfloat16(v - __bfloat162float(h));
    }
}

// ---------------- 3) HMMA split-bf16 NT GEMM -------------------------------
// C[m,n] = sum_k A[m,k]*B[n,k] + bias[n] via Ahi*Bhi + Ahi*Blo + Alo*Bhi.
// CTA 128x128, 8 warps (4 on M x 2 on N), warp tile 32x64, K-chunk 32.
// smem per stage: 4 tiles (Ahi,Alo,Bhi,Blo) of 128 rows x 80B (stride 40 halves).
#define KC        32
#define ROWB      80                       // bytes per smem row (32 bf16 + pad)
#define TILEB     (128 * ROWB)             // 10240 bytes per tile
#define STAGEB    (4 * TILEB)              // 40960
#define GEMM_SMEM (2 * STAGEB)             // 81920

__global__ __launch_bounds__(256) void gemm_hmma(const __nv_bfloat16* __restrict__ Ahi,
                                                 const __nv_bfloat16* __restrict__ Alo,
                                                 const __nv_bfloat16* __restrict__ Bhi,
                                                 const __nv_bfloat16* __restrict__ Blo,
                                                 const float* __restrict__ bias,
                                                 float* __restrict__ C)
{
    extern __shared__ __align__(128) char sm[];
    const uint32_t sbase = smem_u32(sm);

    const int tid  = threadIdx.x;
    const int wid  = tid >> 5;
    const int lane = tid & 31;
    const int m0 = blockIdx.y * 128;
    const int n0 = blockIdx.x * 128;
    const int wm = wid & 3;          // 0..3 -> m rows wm*32
    const int wn = wid >> 2;         // 0..1 -> n cols wn*64

    // ---- load assignment: thread -> (row, 2 chunks of 16B) per tile ----
    const int lrow = tid >> 1;              // 0..127
    const int lcp  = (tid & 1) * 2;         // chunk 0/1 or 2/3
    const uint32_t srow = sbase + (uint32_t)lrow * ROWB + (uint32_t)lcp * 16;
    const __nv_bfloat16* gAh = Ahi + (size_t)(m0 + lrow) * DIM + lcp * 8;
    const __nv_bfloat16* gAl = Alo + (size_t)(m0 + lrow) * DIM + lcp * 8;
    const __nv_bfloat16* gBh = Bhi + (size_t)(n0 + lrow) * DIM + lcp * 8;
    const __nv_bfloat16* gBl = Blo + (size_t)(n0 + lrow) * DIM + lcp * 8;

    float acc[2][8][4];
#pragma unroll
    for (int i = 0; i < 2; i++)
#pragma unroll
        for (int j = 0; j < 8; j++)
#pragma unroll
            for (int e = 0; e < 4; e++) acc[i][j][e] = 0.f;

    const int NCH = DIM / KC;   // 64 chunks

    auto issue = [&](int c) {
        uint32_t b = srow + (uint32_t)(c & 1) * STAGEB;
        const int ko = c * KC;
        cp_async16(b + 0 * TILEB,      gAh + ko);
        cp_async16(b + 0 * TILEB + 16, gAh + ko + 8);
        cp_async16(b + 1 * TILEB,      gAl + ko);
        cp_async16(b + 1 * TILEB + 16, gAl + ko + 8);
        cp_async16(b + 2 * TILEB,      gBh + ko);
        cp_async16(b + 2 * TILEB + 16, gBh + ko + 8);
        cp_async16(b + 3 * TILEB,      gBl + ko);
        cp_async16(b + 3 * TILEB + 16, gBl + ko + 8);
        cp_commit();
    };

    issue(0);
    issue(1);

    // ldmatrix address components for this lane
    const uint32_t lrow16 = (uint32_t)(lane & 15);
    const uint32_t lhalf  = (uint32_t)(lane >> 4) * 16;   // +16B for k+8 matrices

    for (int c = 0; c < NCH; c++) {
        cp_wait<1>();
        __syncthreads();

        const uint32_t st = sbase + (uint32_t)(c & 1) * STAGEB;
        const uint32_t aRow = st + (uint32_t)(wm * 32) * ROWB;
        const uint32_t bRow = st + 2 * TILEB + (uint32_t)(wn * 64) * ROWB;

#pragma unroll
        for (int ks = 0; ks < 2; ks++) {          // two k16 steps in chunk
            const uint32_t kb = (uint32_t)(ks * 32) + lhalf;   // byte offset in row

            uint32_t ah[2][4], al[2][4];
#pragma unroll
            for (int im = 0; im < 2; im++) {
                uint32_t ra = aRow + (im * 16 + lrow16) * ROWB + kb;
                ldsm_x4(ra,            ah[im][0], ah[im][1], ah[im][2], ah[im][3]);
                ldsm_x4(ra + TILEB,    al[im][0], al[im][1], al[im][2], al[im][3]);
            }

#pragma unroll
            for (int in4 = 0; in4 < 4; in4++) {   // n16 groups
                uint32_t rb = bRow + (in4 * 16 + lrow16) * ROWB + kb;
                uint32_t bh0, bh1, bh2, bh3, bl0, bl1, bl2, bl3;
                ldsm_x4(rb,         bh0, bh1, bh2, bh3);
                ldsm_x4(rb + TILEB, bl0, bl1, bl2, bl3);

#pragma unroll
                for (int im = 0; im < 2; im++) {
                    float* c0 = acc[im][in4 * 2];
                    float* c1 = acc[im][in4 * 2 + 1];
                    // hi*hi
                    mma_bf16(c0[0], c0[1], c0[2], c0[3],
                             ah[im][0], ah[im][1], ah[im][2], ah[im][3], bh0, bh2);
                    mma_bf16(c1[0], c1[1], c1[2], c1[3],
                             ah[im][0], ah[im][1], ah[im][2], ah[im][3], bh1, bh3);
                    // hi*lo
                    mma_bf16(c0[0], c0[1], c0[2], c0[3],
                             ah[im][0], ah[im][1], ah[im][2], ah[im][3], bl0, bl2);
                    mma_bf16(c1[0], c1[1], c1[2], c1[3],
                             ah[im][0], ah[im][1], ah[im][2], ah[im][3], bl1, bl3);
                    // lo*hi
                    mma_bf16(c0[0], c0[1], c0[2], c0[3],
                             al[im][0], al[im][1], al[im][2], al[im][3], bh0, bh2);
                    mma_bf16(c1[0], c1[1], c1[2], c1[3],
                             al[im][0], al[im][1], al[im][2], al[im][3], bh1, bh3);
                }
            }
        }
        __syncthreads();
        if (c + 2 < NCH) issue(c + 2);
    }

    // ---- epilogue: fragment -> global with bias ----
    const int r0 = lane >> 2;          // 0..7
    const int cpair = (lane & 3) * 2;  // 0,2,4,6
#pragma unroll
    for (int im = 0; im < 2; im++) {
        const int mrow = m0 + wm * 32 + im * 16 + r0;
#pragma unroll
        for (int jn = 0; jn < 8; jn++) {
            const int col = n0 + wn * 64 + jn * 8 + cpair;
            const float b0 = bias[col], b1 = bias[col + 1];
            float* p0 = C + (size_t)mrow * DIM + col;
            float* p1 = C + (size_t)(mrow + 8) * DIM + col;
            float2 v0 = make_float2(acc[im][jn][0] + b0, acc[im][jn][1] + b1);
            float2 v1 = make_float2(acc[im][jn][2] + b0, acc[im][jn][3] + b1);
            *(float2*)p0 = v0;
            *(float2*)p1 = v1;
        }
    }
}

// ---------------- 4) RMSNorm (over D=2048) + interleaved RoPE, in place ---
__global__ __launch_bounds__(256) void rmsnorm_rope(float* __restrict__ X,
                                                    const float* __restrict__ w,
                                                    const float* __restrict__ fcos,
                                                    const float* __restrict__ fsin)
{
    const int s = blockIdx.x;
    const int tid = threadIdx.x;
    __shared__ float red[256];

    float* row = X + (size_t)s * DIM;
    float ss = 0.f;
#pragma unroll
    for (int i = tid; i < DIM; i += 256) { float v = row[i]; ss += v * v; }
    red[tid] = ss;
    __syncthreads();
    for (int st = 128; st > 0; st >>= 1) {
        if (tid < st) red[tid] += red[tid + st];
        __syncthreads();
    }
    const float rs = rsqrtf(red[0] / (float)DIM + EPS_);

#pragma unroll
    for (int p = tid; p < DIM / 2; p += 256) {
        int hp = p & 63;
        float c  = fcos[s * HD + 2 * hp];
        float sn = fsin[s * HD + 2 * hp + 1];
        float x1 = row[2 * p]     * rs * w[2 * p];
        float x2 = row[2 * p + 1] * rs * w[2 * p + 1];
        row[2 * p]     = x1 * c - x2 * sn;
        row[2 * p + 1] = x1 * sn + x2 * c;
    }
}

// ---------------- 5) flash attention (fp32, online softmax) --------------
#define QS_OFF 0        // [128][68] transposed (Qs[d][r]), pre-scaled
#define KS_OFF 8704     // [128][68] transposed
#define VS_OFF 17408    // [64][128]
#define SS_OFF 25600    // [64][65]
#define MS_OFF 29760    // [64]
#define LS_OFF 29824    // [64]
#define AL_OFF 29888    // [64]
#define FLASH_SMEM_FLOATS 29952

__global__ __launch_bounds__(256) void flash_attn(const float* __restrict__ Q,
                                                  const float* __restrict__ K,
                                                  const float* __restrict__ V,
                                                  float* __restrict__ O)
{
    extern __shared__ float smf[];
    float* smQ = smf + QS_OFF;
    float* smK = smf + KS_OFF;
    float* smV = smf + VS_OFF;
    float* smS = smf + SS_OFF;
    float* smM = smf + MS_OFF;
    float* smL = smf + LS_OFF;
    float* smA = smf + AL_OFF;

    const int tid = threadIdx.x;
    const int qt = blockIdx.x;
    const int h  = blockIdx.y;
    const int tr = tid >> 4;
    const int tc = tid & 15;
    const int tr4 = tr * 4;
    const int tc4 = tc * 4;
    const int tc8 = tc * 8;
    const float scale = 0.08838834764831845f;   // 1/sqrt(128)

    const size_t qbase = (size_t)(qt * 64) * DIM + h * HD;
    for (int e = tid; e < 64 * HD; e += 256) {
        int r = e >> 7, d = e & 127;
        smQ[d * 68 + r] = Q[qbase + (size_t)r * DIM + d] * scale;
    }
    if (tid < 64) { smM[tid] = -1e30f; smL[tid] = 0.f; }

    float acc[4][8] = {};
    __syncthreads();

    for (int kt = 0; kt < SEQ / 64; kt++) {
        const size_t kbase = (size_t)(kt * 64) * DIM + h * HD;
        for (int e = tid; e < 64 * HD; e += 256) {
            int r = e >> 7, d = e & 127;
            smK[d * 68 + r] = K[kbase + (size_t)r * DIM + d];
        }
        for (int e = tid; e < 64 * (HD / 4); e += 256) {
            int r = e >> 5, d4 = (e & 31) * 4;
            *(float4*)&smV[r * HD + d4] = *(const float4*)(V + kbase + (size_t)r * DIM + d4);
        }
        __syncthreads();

        float s4[4][4] = {};
#pragma unroll 8
        for (int k = 0; k < HD; k++) {
            float4 qa = *(const float4*)&smQ[k * 68 + tr4];
            float4 kb = *(const float4*)&smK[k * 68 + tc4];
            float qf[4] = {qa.x, qa.y, qa.z, qa.w};
            float kf[4] = {kb.x, kb.y, kb.z, kb.w};
#pragma unroll
            for (int i = 0; i < 4; i++)
#pragma unroll
                for (int j = 0; j < 4; j++)
                    s4[i][j] += qf[i] * kf[j];
        }
#pragma unroll
        for (int i = 0; i < 4; i++)
#pragma unroll
            for (int j = 0; j < 4; j++)
                smS[(tr4 + i) * 65 + tc4 + j] = s4[i][j];
        __syncthreads();

        if (tid < 64) {
            float* srow = &smS[tid * 65];
            float mold = smM[tid];
            float mx = mold;
#pragma unroll 8
            for (int j = 0; j < 64; j++) mx = fmaxf(mx, srow[j]);
            float alpha = __expf(mold - mx);
            float sum = 0.f;
#pragma unroll 8
            for (int j = 0; j < 64; j++) {
                float p = __expf(srow[j] - mx);
                srow[j] = p;
                sum += p;
            }
            smL[tid] = smL[tid] * alpha + sum;
            smM[tid] = mx;
            smA[tid] = alpha;
        }
        __syncthreads();

        float al[4];
#pragma unroll
        for (int i = 0; i < 4; i++) al[i] = smA[tr4 + i];
#pragma unroll
        for (int i = 0; i < 4; i++)
#pragma unroll
            for (int d = 0; d < 8; d++) acc[i][d] *= al[i];

#pragma unroll 4
        for (int j = 0; j < 64; j++) {
            float4 v0 = *(const float4*)&smV[j * HD + tc8];
            float4 v1 = *(const float4*)&smV[j * HD + tc8 + 4];
#pragma unroll
            for (int i = 0; i < 4; i++) {
                float p = smS[(tr4 + i) * 65 + j];
                acc[i][0] += p * v0.x; acc[i][1] += p * v0.y;
                acc[i][2] += p * v0.z; acc[i][3] += p * v0.w;
                acc[i][4] += p * v1.x; acc[i][5] += p * v1.y;
                acc[i][6] += p * v1.z; acc[i][7] += p * v1.w;
            }
        }
        __syncthreads();
    }

#pragma unroll
    for (int i = 0; i < 4; i++) {
        float inv = 1.0f / smL[tr4 + i];
        float* orow = O + (size_t)(qt * 64 + tr4 + i) * DIM + h * HD + tc8;
        float4 r0 = make_float4(acc[i][0] * inv, acc[i][1] * inv,
                                acc[i][2] * inv, acc[i][3] * inv);
        float4 r1 = make_float4(acc[i][4] * inv, acc[i][5] * inv,
                                acc[i][6] * inv, acc[i][7] * inv);
        *(float4*)(orow)     = r0;
        *(float4*)(orow + 4) = r1;
    }
}

// ---------------- launch ---------------------------------------------------
template <typename T>
static T* symaddr(const void* sym)
{
    void* p = nullptr;
    cudaGetSymbolAddress(&p, sym);
    return (T*)p;
}

extern "C" void kernel_launch(void* const* d_in, const int* in_sizes, int n_in,
                              void* d_out, int out_size)
{
    const float* x       = (const float*)d_in[0];
    const float* wq      = (const float*)d_in[1];
    const float* bq      = (const float*)d_in[2];
    const float* wk      = (const float*)d_in[3];
    const float* bk      = (const float*)d_in[4];
    const float* wv      = (const float*)d_in[5];
    const float* bv      = (const float*)d_in[6];
    const float* wo      = (const float*)d_in[7];
    const float* bo      = (const float*)d_in[8];
    const float* lq_down = (const float*)d_in[9];
    const float* lq_up   = (const float*)d_in[10];
    const float* lk_down = (const float*)d_in[11];
    const float* lk_up   = (const float*)d_in[12];
    const float* lv_down = (const float*)d_in[13];
    const float* lv_up   = (const float*)d_in[14];
    const float* lo_down = (const float*)d_in[15];
    const float* lo_up   = (const float*)d_in[16];
    const float* nq_w    = (const float*)d_in[17];
    const float* nk_w    = (const float*)d_in[18];
    const float* fcos    = (const float*)d_in[19];
    const float* fsin    = (const float*)d_in[20];

    __nv_bfloat16* xhi = symaddr<__nv_bfloat16>(g_xhi);
    __nv_bfloat16* xlo = symaddr<__nv_bfloat16>(g_xlo);
    __nv_bfloat16* whi = symaddr<__nv_bfloat16>(g_whi);
    __nv_bfloat16* wlo = symaddr<__nv_bfloat16>(g_wlo);
    __nv_bfloat16* ohi = symaddr<__nv_bfloat16>(g_ohi);
    __nv_bfloat16* olo = symaddr<__nv_bfloat16>(g_olo);
    float* q = symaddr<float>(g_q);
    float* k = symaddr<float>(g_k);
    float* v = symaddr<float>(g_v);
    float* o = symaddr<float>(g_o);

    cudaFuncSetAttribute(flash_attn, cudaFuncAttributeMaxDynamicSharedMemorySize,
                         FLASH_SMEM_FLOATS * (int)sizeof(float));
    cudaFuncSetAttribute(gemm_hmma, cudaFuncAttributeMaxDynamicSharedMemorySize,
                         GEMM_SMEM);

    const float scale = 16.0f / (float)RANK;   // ALPHA / R = 1.0
    const int   nel   = SEQ * DIM;
    const size_t WSZ  = (size_t)DIM * DIM;

    // 1) splits + effective weights
    split_bf16<<<(nel + 255) / 256, 256>>>(x, xhi, xlo, nel);
    dim3 pg(DIM / 256, DIM);
    prep_weff_split<<<pg, 256>>>(wq, lq_down, lq_up, whi + 0 * WSZ, wlo + 0 * WSZ, scale);
    prep_weff_split<<<pg, 256>>>(wk, lk_down, lk_up, whi + 1 * WSZ, wlo + 1 * WSZ, scale);
    prep_weff_split<<<pg, 256>>>(wv, lv_down, lv_up, whi + 2 * WSZ, wlo + 2 * WSZ, scale);
    prep_weff_split<<<pg, 256>>>(wo, lo_down, lo_up, whi + 3 * WSZ, wlo + 3 * WSZ, scale);

    // 2) QKV projections on HMMA tensor cores
    dim3 gg(DIM / 128, SEQ / 128);
    gemm_hmma<<<gg, 256, GEMM_SMEM>>>(xhi, xlo, whi + 0 * WSZ, wlo + 0 * WSZ, bq, q);
    gemm_hmma<<<gg, 256, GEMM_SMEM>>>(xhi, xlo, whi + 1 * WSZ, wlo + 1 * WSZ, bk, k);
    gemm_hmma<<<gg, 256, GEMM_SMEM>>>(xhi, xlo, whi + 2 * WSZ, wlo + 2 * WSZ, bv, v);

    // 3) norms + rope
    rmsnorm_rope<<<SEQ, 256>>>(q, nq_w, fcos, fsin);
    rmsnorm_rope<<<SEQ, 256>>>(k, nk_w, fcos, fsin);

    // 4) attention (fp32 this round)
    dim3 ag(SEQ / 64, NH);
    flash_attn<<<ag, 256, FLASH_SMEM_FLOATS * sizeof(float)>>>(q, k, v, o);

    // 5) output projection on HMMA tensor cores
    split_bf16<<<(nel + 255) / 256, 256>>>(o, ohi, olo, nel);
    gemm_hmma<<<gg, 256, GEMM_SMEM>>>(ohi, olo, whi + 3 * WSZ, wlo + 3 * WSZ, bo,
                                      (float*)d_out);
}

// round 7
// speedup vs baseline: 2.9986x; 2.2142x over previous
#include <cuda_runtime.h>
#include <cuda_bf16.h>
#include <math.h>
#include <stdint.h>

#define DIM   2048
#define SEQ   3072
#define NH    16
#define HD    128
#define RANK  16
#define EPS_  1e-6f

// ---------------- scratch (static device memory; no allocs) ----------------
__device__ __nv_bfloat16 g_xhi[SEQ * DIM];
__device__ __nv_bfloat16 g_xlo[SEQ * DIM];
__device__ __nv_bfloat16 g_whi[4][DIM * DIM];
__device__ __nv_bfloat16 g_wlo[4][DIM * DIM];
__device__ __nv_bfloat16 g_qhi[SEQ * DIM];
__device__ __nv_bfloat16 g_qlo[SEQ * DIM];
__device__ __nv_bfloat16 g_khi[SEQ * DIM];
__device__ __nv_bfloat16 g_klo[SEQ * DIM];
__device__ __nv_bfloat16 g_vthi[NH * HD * SEQ];
__device__ __nv_bfloat16 g_vtlo[NH * HD * SEQ];
__device__ __nv_bfloat16 g_ohi[SEQ * DIM];
__device__ __nv_bfloat16 g_olo[SEQ * DIM];
__device__ float g_q[SEQ * DIM];
__device__ float g_k[SEQ * DIM];
__device__ float g_v[SEQ * DIM];

// ---------------- PTX helpers ---------------------------------------------
__device__ __forceinline__ uint32_t smem_u32(const void* p)
{
    uint32_t a;
    asm("{ .reg .u64 t; cvta.to.shared.u64 t, %1; cvt.u32.u64 %0, t; }"
        : "=r"(a) : "l"(p));
    return a;
}

__device__ __forceinline__ void cp_async16(uint32_t s, const void* g)
{
    asm volatile("cp.async.cg.shared.global [%0], [%1], 16;" :: "r"(s), "l"(g));
}

__device__ __forceinline__ void cp_commit()
{
    asm volatile("cp.async.commit_group;" ::: "memory");
}

template <int N>
__device__ __forceinline__ void cp_wait()
{
    asm volatile("cp.async.wait_group %0;" :: "n"(N) : "memory");
}

__device__ __forceinline__ void ldsm_x4(uint32_t addr, uint32_t& r0, uint32_t& r1,
                                        uint32_t& r2, uint32_t& r3)
{
    asm volatile("ldmatrix.sync.aligned.m8n8.x4.shared.b16 {%0,%1,%2,%3}, [%4];"
                 : "=r"(r0), "=r"(r1), "=r"(r2), "=r"(r3) : "r"(addr));
}

__device__ __forceinline__ void mma_bf16(float* c,
                                         const uint32_t* a, uint32_t b0, uint32_t b1)
{
    asm volatile(
        "mma.sync.aligned.m16n8k16.row.col.f32.bf16.bf16.f32 "
        "{%0,%1,%2,%3}, {%4,%5,%6,%7}, {%8,%9}, {%0,%1,%2,%3};"
        : "+f"(c[0]), "+f"(c[1]), "+f"(c[2]), "+f"(c[3])
        : "r"(a[0]), "r"(a[1]), "r"(a[2]), "r"(a[3]), "r"(b0), "r"(b1));
}

// ---------------- 1) effective weight prep + bf16 split --------------------
__global__ __launch_bounds__(256) void prep_weff_split(const float* __restrict__ w,
                                                       const float* __restrict__ ldown,
                                                       const float* __restrict__ lup,
                                                       __nv_bfloat16* __restrict__ hi,
                                                       __nv_bfloat16* __restrict__ lo,
                                                       float scale)
{
    int kx = blockIdx.x * 256 + threadIdx.x;
    int j  = blockIdx.y;
    float acc = 0.f;
#pragma unroll
    for (int r = 0; r < RANK; r++)
        acc += lup[j * RANK + r] * ldown[r * DIM + kx];
    float v = w[j * DIM + kx] + scale * acc;
    __nv_bfloat16 h = __float2bfloat16(v);
    hi[j * DIM + kx] = h;
    lo[j * DIM + kx] = __float2bfloat16(v - __bfloat162float(h));
}

// ---------------- 2) fp32 -> bf16 hi/lo split -------------------------------
__global__ __launch_bounds__(256) void split_bf16(const float* __restrict__ in,
                                                  __nv_bfloat16* __restrict__ hi,
                                                  __nv_bfloat16* __restrict__ lo,
                                                  int n)
{
    int i = blockIdx.x * 256 + threadIdx.x;
    if (i < n) {
        float v = in[i];
        __nv_bfloat16 h = __float2bfloat16(v);
        hi[i] = h;
        lo[i] = __float2bfloat16(v - __bfloat162float(h));
    }
}

// ---------------- 3) HMMA split-bf16 NT GEMM -------------------------------
#define KC        32
#define ROWB      80
#define TILEB     (128 * ROWB)
#define STAGEB    (4 * TILEB)
#define GEMM_SMEM (2 * STAGEB)

__global__ __launch_bounds__(256) void gemm_hmma(const __nv_bfloat16* __restrict__ Ahi,
                                                 const __nv_bfloat16* __restrict__ Alo,
                                                 const __nv_bfloat16* __restrict__ Bhi,
                                                 const __nv_bfloat16* __restrict__ Blo,
                                                 const float* __restrict__ bias,
                                                 float* __restrict__ C)
{
    extern __shared__ __align__(128) char sm[];
    const uint32_t sbase = smem_u32(sm);

    const int tid  = threadIdx.x;
    const int wid  = tid >> 5;
    const int lane = tid & 31;
    const int m0 = blockIdx.y * 128;
    const int n0 = blockIdx.x * 128;
    const int wm = wid & 3;
    const int wn = wid >> 2;

    const int lrow = tid >> 1;
    const int lcp  = (tid & 1) * 2;
    const uint32_t srow = sbase + (uint32_t)lrow * ROWB + (uint32_t)lcp * 16;
    const __nv_bfloat16* gAh = Ahi + (size_t)(m0 + lrow) * DIM + lcp * 8;
    const __nv_bfloat16* gAl = Alo + (size_t)(m0 + lrow) * DIM + lcp * 8;
    const __nv_bfloat16* gBh = Bhi + (size_t)(n0 + lrow) * DIM + lcp * 8;
    const __nv_bfloat16* gBl = Blo + (size_t)(n0 + lrow) * DIM + lcp * 8;

    float acc[2][8][4];
#pragma unroll
    for (int i = 0; i < 2; i++)
#pragma unroll
        for (int j = 0; j < 8; j++)
#pragma unroll
            for (int e = 0; e < 4; e++) acc[i][j][e] = 0.f;

    const int NCH = DIM / KC;

    auto issue = [&](int c) {
        uint32_t b = srow + (uint32_t)(c & 1) * STAGEB;
        const int ko = c * KC;
        cp_async16(b + 0 * TILEB,      gAh + ko);
        cp_async16(b + 0 * TILEB + 16, gAh + ko + 8);
        cp_async16(b + 1 * TILEB,      gAl + ko);
        cp_async16(b + 1 * TILEB + 16, gAl + ko + 8);
        cp_async16(b + 2 * TILEB,      gBh + ko);
        cp_async16(b + 2 * TILEB + 16, gBh + ko + 8);
        cp_async16(b + 3 * TILEB,      gBl + ko);
        cp_async16(b + 3 * TILEB + 16, gBl + ko + 8);
        cp_commit();
    };

    issue(0);
    issue(1);

    const uint32_t lrow16 = (uint32_t)(lane & 15);
    const uint32_t lhalf  = (uint32_t)(lane >> 4) * 16;

    for (int c = 0; c < NCH; c++) {
        if (c == NCH - 1) cp_wait<0>(); else cp_wait<1>();
        __syncthreads();

        const uint32_t st = sbase + (uint32_t)(c & 1) * STAGEB;
        const uint32_t aRow = st + (uint32_t)(wm * 32) * ROWB;
        const uint32_t bRow = st + 2 * TILEB + (uint32_t)(wn * 64) * ROWB;

#pragma unroll
        for (int ks = 0; ks < 2; ks++) {
            const uint32_t kb = (uint32_t)(ks * 32) + lhalf;

            uint32_t ah[2][4], al[2][4];
#pragma unroll
            for (int im = 0; im < 2; im++) {
                uint32_t ra = aRow + (im * 16 + lrow16) * ROWB + kb;
                ldsm_x4(ra,         ah[im][0], ah[im][1], ah[im][2], ah[im][3]);
                ldsm_x4(ra + TILEB, al[im][0], al[im][1], al[im][2], al[im][3]);
            }

#pragma unroll
            for (int in4 = 0; in4 < 4; in4++) {
                uint32_t rb = bRow + (in4 * 16 + lrow16) * ROWB + kb;
                uint32_t bh0, bh1, bh2, bh3, bl0, bl1, bl2, bl3;
                ldsm_x4(rb,         bh0, bh1, bh2, bh3);
                ldsm_x4(rb + TILEB, bl0, bl1, bl2, bl3);

#pragma unroll
                for (int im = 0; im < 2; im++) {
                    float* c0 = acc[im][in4 * 2];
                    float* c1 = acc[im][in4 * 2 + 1];
                    mma_bf16(c0, ah[im], bh0, bh2);
                    mma_bf16(c1, ah[im], bh1, bh3);
                    mma_bf16(c0, ah[im], bl0, bl2);
                    mma_bf16(c1, ah[im], bl1, bl3);
                    mma_bf16(c0, al[im], bh0, bh2);
                    mma_bf16(c1, al[im], bh1, bh3);
                }
            }
        }
        __syncthreads();
        if (c + 2 < NCH) issue(c + 2);
    }

    const int r0 = lane >> 2;
    const int cpair = (lane & 3) * 2;
#pragma unroll
    for (int im = 0; im < 2; im++) {
        const int mrow = m0 + wm * 32 + im * 16 + r0;
#pragma unroll
        for (int jn = 0; jn < 8; jn++) {
            const int col = n0 + wn * 64 + jn * 8 + cpair;
            const float b0 = bias[col], b1 = bias[col + 1];
            float* p0 = C + (size_t)mrow * DIM + col;
            float* p1 = C + (size_t)(mrow + 8) * DIM + col;
            *(float2*)p0 = make_float2(acc[im][jn][0] + b0, acc[im][jn][1] + b1);
            *(float2*)p1 = make_float2(acc[im][jn][2] + b0, acc[im][jn][3] + b1);
        }
    }
}

// ---------------- 4) RMSNorm + RoPE + bf16 hi/lo split ---------------------
__global__ __launch_bounds__(256) void rmsnorm_rope_split(const float* __restrict__ X,
                                                          const float* __restrict__ w,
                                                          const float* __restrict__ fcos,
                                                          const float* __restrict__ fsin,
                                                          __nv_bfloat16* __restrict__ hi,
                                                          __nv_bfloat16* __restrict__ lo,
                                                          float outscale)
{
    const int s = blockIdx.x;
    const int tid = threadIdx.x;
    __shared__ float red[256];

    const float* row = X + (size_t)s * DIM;
    float ss = 0.f;
#pragma unroll
    for (int i = tid; i < DIM; i += 256) { float v = row[i]; ss += v * v; }
    red[tid] = ss;
    __syncthreads();
    for (int st = 128; st > 0; st >>= 1) {
        if (tid < st) red[tid] += red[tid + st];
        __syncthreads();
    }
    const float rs = rsqrtf(red[0] / (float)DIM + EPS_);

#pragma unroll
    for (int p = tid; p < DIM / 2; p += 256) {
        int hp = p & 63;
        float c  = fcos[s * HD + 2 * hp];
        float sn = fsin[s * HD + 2 * hp + 1];
        float x1 = row[2 * p]     * rs * w[2 * p];
        float x2 = row[2 * p + 1] * rs * w[2 * p + 1];
        float e = (x1 * c - x2 * sn) * outscale;
        float o = (x1 * sn + x2 * c) * outscale;
        __nv_bfloat16 eh = __float2bfloat16(e);
        __nv_bfloat16 oh = __float2bfloat16(o);
        hi[(size_t)s * DIM + 2 * p]     = eh;
        hi[(size_t)s * DIM + 2 * p + 1] = oh;
        lo[(size_t)s * DIM + 2 * p]     = __float2bfloat16(e - __bfloat162float(eh));
        lo[(size_t)s * DIM + 2 * p + 1] = __float2bfloat16(o - __bfloat162float(oh));
    }
}

// ---------------- 5) V transpose + split: [s][h*128+d] -> [h][d][s] --------
__global__ __launch_bounds__(256) void vtrans_split(const float* __restrict__ V,
                                                    __nv_bfloat16* __restrict__ vthi,
                                                    __nv_bfloat16* __restrict__ vtlo)
{
    __shared__ float t[32][33];
    const int s0 = blockIdx.x * 32;
    const int d0 = blockIdx.y * 32;
    const int h  = blockIdx.z;
    const int tx = threadIdx.x;        // 0..31
    const int ty = threadIdx.y;        // 0..7

    for (int i = ty; i < 32; i += 8)
        t[i][tx] = V[(size_t)(s0 + i) * DIM + h * HD + d0 + tx];
    __syncthreads();
    for (int i = ty; i < 32; i += 8) {
        float v = t[tx][i];
        __nv_bfloat16 hv = __float2bfloat16(v);
        size_t idx = (size_t)h * HD * SEQ + (size_t)(d0 + i) * SEQ + s0 + tx;
        vthi[idx] = hv;
        vtlo[idx] = __float2bfloat16(v - __bfloat162float(hv));
    }
}

// ---------------- 6) tensor-core flash attention (split-bf16) --------------
// CTA: 64 q-rows x 1 head, 256 threads (8 warps: wm=wid&3, wn=wid>>2).
// smem byte offsets:
#define FA_KB   0                        // K stages: 2 x (hi 17408 + lo 17408)
#define FA_VB   69632                    // V stages: 2 x (hi 18432 + lo 18432)
#define FA_SS   143360                   // S fp32 [64][68]  (also Q staging)
#define FA_PH   160768                   // P hi bf16 [64] rows stride 144
#define FA_PL   169984                   // P lo
#define FA_MM   179200                   // m[64] fp32
#define FA_LL   179456                   // l[64]
#define FA_AA   179712                   // alpha[64]
#define FA_SMEM 179968
#define KROWB   272                      // 256B + 16 pad
#define VROWB   144                      // 128B + 16 pad
#define NKT     (SEQ / 64)

__global__ __launch_bounds__(256, 1) void flash_attn_tc(
    const __nv_bfloat16* __restrict__ qhi, const __nv_bfloat16* __restrict__ qlo,
    const __nv_bfloat16* __restrict__ khi, const __nv_bfloat16* __restrict__ klo,
    const __nv_bfloat16* __restrict__ vthi, const __nv_bfloat16* __restrict__ vtlo,
    __nv_bfloat16* __restrict__ ohi, __nv_bfloat16* __restrict__ olo)
{
    extern __shared__ __align__(128) char sm[];
    const uint32_t sb = smem_u32(sm);
    const int tid  = threadIdx.x;
    const int wid  = tid >> 5;
    const int lane = tid & 31;
    const int qt = blockIdx.x;
    const int h  = blockIdx.y;
    const int wm = wid & 3;
    const int wn = wid >> 2;
    const uint32_t lrow16 = (uint32_t)(lane & 15);
    const uint32_t lhalf  = (uint32_t)(lane >> 4) * 16;
    const int r0 = lane >> 2;
    const int c2 = (lane & 3) * 2;

    float* smM = (float*)(sm + FA_MM);
    float* smL = (float*)(sm + FA_LL);
    float* smA = (float*)(sm + FA_AA);

    // ---- stage Q (hi then lo) through FA_SS, load fragments to registers --
    uint32_t qh[8][4], ql[8][4];
    const size_t qoff = (size_t)(qt * 64) * DIM + h * HD;
#pragma unroll
    for (int pass = 0; pass < 2; pass++) {
        const __nv_bfloat16* src = (pass == 0) ? (qhi + qoff) : (qlo + qoff);
        for (int c = tid; c < 1024; c += 256) {
            int row = c >> 4, o16 = c & 15;
            *(uint4*)(sm + FA_SS + row * KROWB + o16 * 16) =
                *(const uint4*)(src + (size_t)row * DIM + o16 * 8);
        }
        __syncthreads();
#pragma unroll
        for (int kk = 0; kk < 8; kk++) {
            uint32_t ra = sb + FA_SS + (wm * 16 + lrow16) * KROWB + kk * 32 + lhalf;
            if (pass == 0) ldsm_x4(ra, qh[kk][0], qh[kk][1], qh[kk][2], qh[kk][3]);
            else           ldsm_x4(ra, ql[kk][0], ql[kk][1], ql[kk][2], ql[kk][3]);
        }
        __syncthreads();
    }
    if (tid < 64) { smM[tid] = -1e30f; smL[tid] = 0.f; }

    float oa[8][4];
#pragma unroll
    for (int g = 0; g < 8; g++)
#pragma unroll
        for (int e = 0; e < 4; e++) oa[g][e] = 0.f;

    auto issue = [&](int kt) {
        const uint32_t stg = (uint32_t)(kt & 1);
        // K tile: 64 rows x 256B, hi+lo
        for (int i = 0; i < 4; i++) {
            int c = tid + i * 256;
            int row = c >> 4, o16 = c & 15;
            const size_t g = (size_t)(kt * 64 + row) * DIM + h * HD + o16 * 8;
            uint32_t d = sb + FA_KB + stg * 34816 + row * KROWB + o16 * 16;
            cp_async16(d,         khi + g);
            cp_async16(d + 17408, klo + g);
        }
        // V tile: 128 d-rows x 128B, hi+lo
        for (int i = 0; i < 4; i++) {
            int c = tid + i * 256;
            int row = c >> 3, o16 = c & 7;
            const size_t g = (size_t)h * HD * SEQ + (size_t)row * SEQ + kt * 64 + o16 * 8;
            uint32_t d = sb + FA_VB + stg * 36864 + row * VROWB + o16 * 16;
            cp_async16(d,         vthi + g);
            cp_async16(d + 18432, vtlo + g);
        }
        cp_commit();
    };

    issue(0);
    issue(1);

    for (int kt = 0; kt < NKT; kt++) {
        if (kt == NKT - 1) cp_wait<0>(); else cp_wait<1>();
        __syncthreads();
        const uint32_t kbS = sb + FA_KB + (uint32_t)(kt & 1) * 34816;
        const uint32_t vbS = sb + FA_VB + (uint32_t)(kt & 1) * 36864;

        // ---- S = Q K^T (warp: 16m x 32n) ----
        float s[4][4];
#pragma unroll
        for (int g = 0; g < 4; g++)
#pragma unroll
            for (int e = 0; e < 4; e++) s[g][e] = 0.f;

#pragma unroll
        for (int kk = 0; kk < 8; kk++) {
#pragma unroll
            for (int in16 = 0; in16 < 2; in16++) {
                uint32_t ra = kbS + (wn * 32 + in16 * 16 + lrow16) * KROWB + kk * 32 + lhalf;
                uint32_t kh0, kh1, kh2, kh3, kl0, kl1, kl2, kl3;
                ldsm_x4(ra,         kh0, kh1, kh2, kh3);
                ldsm_x4(ra + 17408, kl0, kl1, kl2, kl3);
                mma_bf16(s[in16 * 2],     qh[kk], kh0, kh2);
                mma_bf16(s[in16 * 2 + 1], qh[kk], kh1, kh3);
                mma_bf16(s[in16 * 2],     qh[kk], kl0, kl2);
                mma_bf16(s[in16 * 2 + 1], qh[kk], kl1, kl3);
                mma_bf16(s[in16 * 2],     ql[kk], kh0, kh2);
                mma_bf16(s[in16 * 2 + 1], ql[kk], kh1, kh3);
            }
        }
        // store S fragments to smem fp32 [64][68]
#pragma unroll
        for (int g = 0; g < 4; g++) {
            int col = wn * 32 + (g >> 1) * 16 + (g & 1) * 8 + c2;
            int row = wm * 16 + r0;
            *(float2*)(sm + FA_SS + row * KROWB + col * 4)       = make_float2(s[g][0], s[g][1]);
            *(float2*)(sm + FA_SS + (row + 8) * KROWB + col * 4) = make_float2(s[g][2], s[g][3]);
        }
        __syncthreads();

        // ---- online softmax: 4 threads per row ----
        {
            const int row = tid >> 2, seg = tid & 3;
            const float* sr = (const float*)(sm + FA_SS + row * KROWB + seg * 64);
            float v[16];
#pragma unroll
            for (int i = 0; i < 4; i++) {
                float4 f = *(const float4*)(sr + i * 4);
                v[i * 4] = f.x; v[i * 4 + 1] = f.y; v[i * 4 + 2] = f.z; v[i * 4 + 3] = f.w;
            }
            float mloc = v[0];
#pragma unroll
            for (int i = 1; i < 16; i++) mloc = fmaxf(mloc, v[i]);
            mloc = fmaxf(mloc, __shfl_xor_sync(0xffffffffu, mloc, 1));
            mloc = fmaxf(mloc, __shfl_xor_sync(0xffffffffu, mloc, 2));
            const float mold = smM[row];
            const float mx = fmaxf(mold, mloc);
            const float alpha = __expf(mold - mx);
            float sum = 0.f;
            __nv_bfloat162* dh = (__nv_bfloat162*)(sm + FA_PH + row * VROWB + seg * 32);
            __nv_bfloat162* dl = (__nv_bfloat162*)(sm + FA_PL + row * VROWB + seg * 32);
#pragma unroll
            for (int i = 0; i < 8; i++) {
                float p0 = __expf(v[2 * i]     - mx);
                float p1 = __expf(v[2 * i + 1] - mx);
                sum += p0 + p1;
                __nv_bfloat16 h0 = __float2bfloat16(p0);
                __nv_bfloat16 h1 = __float2bfloat16(p1);
                dh[i] = __nv_bfloat162(h0, h1);
                dl[i] = __nv_bfloat162(__float2bfloat16(p0 - __bfloat162float(h0)),
                                       __float2bfloat16(p1 - __bfloat162float(h1)));
            }
            sum += __shfl_xor_sync(0xffffffffu, sum, 1);
            sum += __shfl_xor_sync(0xffffffffu, sum, 2);
            if (seg == 0) {
                smM[row] = mx;
                smL[row] = smL[row] * alpha + sum;
                smA[row] = alpha;
            }
        }
        __syncthreads();

        // ---- rescale O, then O += P V (warp: 16m x 64n) ----
        {
            const float a0 = smA[wm * 16 + r0];
            const float a1 = smA[wm * 16 + r0 + 8];
#pragma unroll
            for (int g = 0; g < 8; g++) {
                oa[g][0] *= a0; oa[g][1] *= a0;
                oa[g][2] *= a1; oa[g][3] *= a1;
            }
        }
#pragma unroll
        for (int j = 0; j < 4; j++) {
            uint32_t pa = sb + FA_PH + (wm * 16 + lrow16) * VROWB + j * 32 + lhalf;
            uint32_t ph[4], pl[4];
            ldsm_x4(pa,                   ph[0], ph[1], ph[2], ph[3]);
            ldsm_x4(pa + (FA_PL - FA_PH), pl[0], pl[1], pl[2], pl[3]);
#pragma unroll
            for (int g = 0; g < 4; g++) {
                uint32_t va = vbS + (wn * 64 + g * 16 + lrow16) * VROWB + j * 32 + lhalf;
                uint32_t vh0, vh1, vh2, vh3, vl0, vl1, vl2, vl3;
                ldsm_x4(va,         vh0, vh1, vh2, vh3);
                ldsm_x4(va + 18432, vl0, vl1, vl2, vl3);
                mma_bf16(oa[g * 2],     ph, vh0, vh2);
                mma_bf16(oa[g * 2 + 1], ph, vh1, vh3);
                mma_bf16(oa[g * 2],     ph, vl0, vl2);
                mma_bf16(oa[g * 2 + 1], ph, vl1, vl3);
                mma_bf16(oa[g * 2],     pl, vh0, vh2);
                mma_bf16(oa[g * 2 + 1], pl, vh1, vh3);
            }
        }
        __syncthreads();
        if (kt + 2 < NKT) issue(kt + 2);
    }

    // ---- epilogue: O/l -> bf16 hi/lo global ----
    const float inv0 = 1.0f / smL[wm * 16 + r0];
    const float inv1 = 1.0f / smL[wm * 16 + r0 + 8];
    const int row0 = qt * 64 + wm * 16 + r0;
#pragma unroll
    for (int g = 0; g < 8; g++) {
        const int col = wn * 64 + (g >> 1) * 16 + (g & 1) * 8 + c2;
        const size_t i0 = (size_t)row0 * DIM + h * HD + col;
        const size_t i1 = (size_t)(row0 + 8) * DIM + h * HD + col;
        float v0 = oa[g][0] * inv0, v1 = oa[g][1] * inv0;
        float v2 = oa[g][2] * inv1, v3 = oa[g][3] * inv1;
        __nv_bfloat16 h0 = __float2bfloat16(v0), h1 = __float2bfloat16(v1);
        __nv_bfloat16 h2 = __float2bfloat16(v2), h3 = __float2bfloat16(v3);
        *(__nv_bfloat162*)(ohi + i0) = __nv_bfloat162(h0, h1);
        *(__nv_bfloat162*)(ohi + i1) = __nv_bfloat162(h2, h3);
        *(__nv_bfloat162*)(olo + i0) =
            __nv_bfloat162(__float2bfloat16(v0 - __bfloat162float(h0)),
                           __float2bfloat16(v1 - __bfloat162float(h1)));
        *(__nv_bfloat162*)(olo + i1) =
            __nv_bfloat162(__float2bfloat16(v2 - __bfloat162float(h2)),
                           __float2bfloat16(v3 - __bfloat162float(h3)));
    }
}

// ---------------- launch ---------------------------------------------------
template <typename T>
static T* symaddr(const void* sym)
{
    void* p = nullptr;
    cudaGetSymbolAddress(&p, sym);
    return (T*)p;
}

extern "C" void kernel_launch(void* const* d_in, const int* in_sizes, int n_in,
                              void* d_out, int out_size)
{
    const float* x       = (const float*)d_in[0];
    const float* wq      = (const float*)d_in[1];
    const float* bq      = (const float*)d_in[2];
    const float* wk      = (const float*)d_in[3];
    const float* bk      = (const float*)d_in[4];
    const float* wv      = (const float*)d_in[5];
    const float* bv      = (const float*)d_in[6];
    const float* wo      = (const float*)d_in[7];
    const float* bo      = (const float*)d_in[8];
    const float* lq_down = (const float*)d_in[9];
    const float* lq_up   = (const float*)d_in[10];
    const float* lk_down = (const float*)d_in[11];
    const float* lk_up   = (const float*)d_in[12];
    const float* lv_down = (const float*)d_in[13];
    const float* lv_up   = (const float*)d_in[14];
    const float* lo_down = (const float*)d_in[15];
    const float* lo_up   = (const float*)d_in[16];
    const float* nq_w    = (const float*)d_in[17];
    const float* nk_w    = (const float*)d_in[18];
    const float* fcos    = (const float*)d_in[19];
    const float* fsin    = (const float*)d_in[20];

    __nv_bfloat16* xhi = symaddr<__nv_bfloat16>(g_xhi);
    __nv_bfloat16* xlo = symaddr<__nv_bfloat16>(g_xlo);
    __nv_bfloat16* whi = symaddr<__nv_bfloat16>(g_whi);
    __nv_bfloat16* wlo = symaddr<__nv_bfloat16>(g_wlo);
    __nv_bfloat16* qhi = symaddr<__nv_bfloat16>(g_qhi);
    __nv_bfloat16* qlo = symaddr<__nv_bfloat16>(g_qlo);
    __nv_bfloat16* khi = symaddr<__nv_bfloat16>(g_khi);
    __nv_bfloat16* klo = symaddr<__nv_bfloat16>(g_klo);
    __nv_bfloat16* vthi = symaddr<__nv_bfloat16>(g_vthi);
    __nv_bfloat16* vtlo = symaddr<__nv_bfloat16>(g_vtlo);
    __nv_bfloat16* ohi = symaddr<__nv_bfloat16>(g_ohi);
    __nv_bfloat16* olo = symaddr<__nv_bfloat16>(g_olo);
    float* q = symaddr<float>(g_q);
    float* k = symaddr<float>(g_k);
    float* v = symaddr<float>(g_v);

    cudaFuncSetAttribute(gemm_hmma, cudaFuncAttributeMaxDynamicSharedMemorySize,
                         GEMM_SMEM);
    cudaFuncSetAttribute(flash_attn_tc, cudaFuncAttributeMaxDynamicSharedMemorySize,
                         FA_SMEM);

    const float scale = 16.0f / (float)RANK;   // ALPHA / R = 1.0
    const int   nel   = SEQ * DIM;
    const size_t WSZ  = (size_t)DIM * DIM;

    // 1) splits + effective weights
    split_bf16<<<(nel + 255) / 256, 256>>>(x, xhi, xlo, nel);
    dim3 pg(DIM / 256, DIM);
    prep_weff_split<<<pg, 256>>>(wq, lq_down, lq_up, whi + 0 * WSZ, wlo + 0 * WSZ, scale);
    prep_weff_split<<<pg, 256>>>(wk, lk_down, lk_up, whi + 1 * WSZ, wlo + 1 * WSZ, scale);
    prep_weff_split<<<pg, 256>>>(wv, lv_down, lv_up, whi + 2 * WSZ, wlo + 2 * WSZ, scale);
    prep_weff_split<<<pg, 256>>>(wo, lo_down, lo_up, whi + 3 * WSZ, wlo + 3 * WSZ, scale);

    // 2) QKV projections (HMMA)
    dim3 gg(DIM / 128, SEQ / 128);
    gemm_hmma<<<gg, 256, GEMM_SMEM>>>(xhi, xlo, whi + 0 * WSZ, wlo + 0 * WSZ, bq, q);
    gemm_hmma<<<gg, 256, GEMM_SMEM>>>(xhi, xlo, whi + 1 * WSZ, wlo + 1 * WSZ, bk, k);
    gemm_hmma<<<gg, 256, GEMM_SMEM>>>(xhi, xlo, whi + 2 * WSZ, wlo + 2 * WSZ, bv, v);

    // 3) norm+rope -> bf16 splits (Q pre-scaled by 1/sqrt(HD)); V transpose-split
    rmsnorm_rope_split<<<SEQ, 256>>>(q, nq_w, fcos, fsin, qhi, qlo,
                                     0.08838834764831845f);
    rmsnorm_rope_split<<<SEQ, 256>>>(k, nk_w, fcos, fsin, khi, klo, 1.0f);
    dim3 vg(SEQ / 32, HD / 32, NH);
    vtrans_split<<<vg, dim3(32, 8)>>>(v, vthi, vtlo);

    // 4) tensor-core flash attention -> bf16 hi/lo O
    dim3 ag(SEQ / 64, NH);
    flash_attn_tc<<<ag, 256, FA_SMEM>>>(qhi, qlo, khi, klo, vthi, vtlo, ohi, olo);

    // 5) output projection (HMMA)
    gemm_hmma<<<gg, 256, GEMM_SMEM>>>(ohi, olo, whi + 3 * WSZ, wlo + 3 * WSZ, bo,
                                      (float*)d_out);
}